// round 13
// baseline (speedup 1.0000x reference)
#include <cuda_runtime.h>
#include <cuda_fp16.h>
#include <math.h>

#define Hh 1024
#define Ww 1024
#define Cc 16
#define HW (1024*1024)

#define ZD (-0.26794919243112270647)   // sqrt(3) - 2

static __device__ __half g_tmp[Cc*HW];     // row-filtered image fp16 (plane layout)
static __device__ __half g_coefh[Cc*HW];   // prefiltered coefs fp16, [group][y][x][4ch]
static __device__ float  g_zp[34];         // z^i
static __device__ float4 g_wy4[1024];      // strict cubic weights per coordinate
static __device__ int    g_myp[1024];      // packed mirrored indices (2 bits x 4)
static __device__ float  g_R[6*1024];      // folded x-dir displacement rows [ch*3+j][x]

// --- exact reference 3-point spline_filter1d (horizon = 3), eager-mode fp32 --
__device__ __forceinline__ void filt3(float v0, float v1, float v2, float* o) {
    const float Zf    = (float)ZD;
    const float Z2f   = (float)(ZD*ZD);
    const float GAIN  = 6.0f;                      // (1-z)(1-1/z) = 6 exactly
    const float LASTC = (float)(ZD/(ZD*ZD-1.0));
    float c0 = __fmul_rn(v0, GAIN);
    float c1 = __fmul_rn(v1, GAIN);
    float c2 = __fmul_rn(v2, GAIN);
    float cp0 = c0;
    cp0 = __fmaf_rn(Zf,  c1, cp0);
    cp0 = __fmaf_rn(Z2f, c2, cp0);
    float cp1 = __fadd_rn(c1, __fmul_rn(Zf, cp0));
    float cp2 = __fadd_rn(c2, __fmul_rn(Zf, cp1));
    float last = __fmul_rn(LASTC, __fadd_rn(cp2, __fmul_rn(Zf, cp1)));
    float o1 = __fmul_rn(Zf, __fsub_rn(last, cp1));
    float o0 = __fmul_rn(Zf, __fsub_rn(o1,  cp0));
    o[0] = o0; o[1] = o1; o[2] = last;
}

// --- strict (eager-jax) cubic weights ----------------------------------------
__device__ __forceinline__ void cubw_strict(float f, float* w) {
    float f2 = __fmul_rn(f, f);
    float f3 = __fmul_rn(f2, f);
    float t = __fsub_rn(1.0f, __fmul_rn(3.0f, f));
    t = __fadd_rn(t, __fmul_rn(3.0f, f2));
    t = __fsub_rn(t, f3);
    w[0] = __fdiv_rn(t, 6.0f);
    t = __fsub_rn(4.0f, __fmul_rn(6.0f, f2));
    t = __fadd_rn(t, __fmul_rn(3.0f, f3));
    w[1] = __fdiv_rn(t, 6.0f);
    t = __fadd_rn(1.0f, __fmul_rn(3.0f, f));
    t = __fadd_rn(t, __fmul_rn(3.0f, f2));
    t = __fsub_rn(t, __fmul_rn(3.0f, f3));
    w[2] = __fdiv_rn(t, 6.0f);
    w[3] = __fdiv_rn(f3, 6.0f);
}

__device__ __forceinline__ int mir3(int i) {        // mirror, n=3 (period 4)
    int m = i < 0 ? -i : i;
    m &= 3;
    return m > 2 ? 4 - m : m;
}
__device__ __forceinline__ int refl1024(int i) {    // mirror, n=1024 (small excursions)
    return i < 0 ? -i : (i > 1023 ? 2046 - i : i);
}

// --- fused setup + tables + z-power table ------------------------------------
__global__ void table_kernel(const float* __restrict__ disp) {
    __shared__ float dcoef[18];
    if (threadIdx.x == 0) {
        if (blockIdx.x == 0) {
            double zp = 1.0;
            for (int i = 0; i < 34; i++) { g_zp[i] = (float)zp; zp *= ZD; }
        }
        float d[2][3][3];
        for (int ch = 0; ch < 2; ch++)
            for (int i = 0; i < 3; i++)
                for (int j = 0; j < 3; j++)
                    d[ch][i][j] = __fmul_rn(disp[ch*9 + i*3 + j], 10.0f);   // SIGMA
        for (int ch = 0; ch < 2; ch++)
            for (int j = 0; j < 3; j++) {
                float o[3];
                filt3(d[ch][0][j], d[ch][1][j], d[ch][2][j], o);
                d[ch][0][j] = o[0]; d[ch][1][j] = o[1]; d[ch][2][j] = o[2];
            }
        for (int ch = 0; ch < 2; ch++)
            for (int i = 0; i < 3; i++) {
                float o[3];
                filt3(d[ch][i][0], d[ch][i][1], d[ch][i][2], o);
                dcoef[ch*9 + i*3 + 0] = o[0];
                dcoef[ch*9 + i*3 + 1] = o[1];
                dcoef[ch*9 + i*3 + 2] = o[2];
            }
    }
    __syncthreads();

    int i = blockIdx.x * 256 + threadIdx.x;         // coordinate 0..1023
    const float SCL = (float)(2.0/1023.0);
    float u = __fmul_rn((float)i, SCL);
    float fl = floorf(u); int i0 = (int)fl;
    float f = __fsub_rn(u, fl);
    float w[4];
    cubw_strict(f, w);
    int m[4];
    #pragma unroll
    for (int b = 0; b < 4; b++) m[b] = mir3(i0 + b - 1);
    g_wy4[i] = make_float4(w[0], w[1], w[2], w[3]);
    g_myp[i] = m[0] | (m[1] << 2) | (m[2] << 4) | (m[3] << 6);
    #pragma unroll
    for (int ch = 0; ch < 2; ch++)
        #pragma unroll
        for (int j = 0; j < 3; j++) {
            float r = 0.0f;
            #pragma unroll
            for (int b = 0; b < 4; b++)
                r = __fadd_rn(r, __fmul_rn(w[b], dcoef[ch*9 + j*3 + m[b]]));
            g_R[(ch*3 + j)*1024 + i] = r;
        }
}

// --- strict dense field at (y, x) — verified bit-identical to reference ------
__device__ __forceinline__ void dense_field(int x, int y, float& sy, float& sx) {
    float4 wy = g_wy4[y];
    int mp = g_myp[y];
    const float* Rx = g_R + x;
    float d0 = 0.0f, d1 = 0.0f;
    int j;
    j = mp & 3;
    d0 = __fadd_rn(d0, __fmul_rn(wy.x, __ldg(Rx + j*1024)));
    d1 = __fadd_rn(d1, __fmul_rn(wy.x, __ldg(Rx + (3+j)*1024)));
    j = (mp >> 2) & 3;
    d0 = __fadd_rn(d0, __fmul_rn(wy.y, __ldg(Rx + j*1024)));
    d1 = __fadd_rn(d1, __fmul_rn(wy.y, __ldg(Rx + (3+j)*1024)));
    j = (mp >> 4) & 3;
    d0 = __fadd_rn(d0, __fmul_rn(wy.z, __ldg(Rx + j*1024)));
    d1 = __fadd_rn(d1, __fmul_rn(wy.z, __ldg(Rx + (3+j)*1024)));
    j = (mp >> 6) & 3;
    d0 = __fadd_rn(d0, __fmul_rn(wy.w, __ldg(Rx + j*1024)));
    d1 = __fadd_rn(d1, __fmul_rn(wy.w, __ldg(Rx + (3+j)*1024)));
    sy = __fadd_rn((float)y, d0);
    sx = __fadd_rn((float)x, d1);
}

// --- row prefilter (along x): warp per row, shuffle scan, fp16 output --------
__global__ void __launch_bounds__(256) rowfilt_kernel(const float* __restrict__ img) {
    int warp = blockIdx.x * 8 + (threadIdx.x >> 5);   // 0 .. 16383  (c*1024 + y)
    int lane = threadIdx.x & 31;
    const float* row = img + warp * Ww;
    __half* orow = g_tmp + warp * Ww;

    const float z1  = (float)ZD;
    const float z2  = (float)(ZD*ZD);
    const float z4  = (float)(ZD*ZD*ZD*ZD);
    const float z8  = (float)(ZD*ZD*ZD*ZD*ZD*ZD*ZD*ZD);
    const float z16 = z8*z8;
    const float SQ3 = (float)((1.0-ZD)/(1.0+ZD));   // sqrt(3)

    float zl1 = g_zp[lane + 1];    // z^(lane+1)
    float zr  = g_zp[32 - lane];   // z^(32-lane)
    float zl0 = g_zp[lane];        // z^lane

    float xs[32], As[32];
    float carry = 0.0f;

    #pragma unroll
    for (int b = 0; b < 32; b++) {
        float x = row[b*32 + lane];
        xs[b] = x;
        float a = x, v;
        v = __shfl_up_sync(0xffffffffu, a, 1);  if (lane >= 1)  a += z1  * v;
        v = __shfl_up_sync(0xffffffffu, a, 2);  if (lane >= 2)  a += z2  * v;
        v = __shfl_up_sync(0xffffffffu, a, 4);  if (lane >= 4)  a += z4  * v;
        v = __shfl_up_sync(0xffffffffu, a, 8);  if (lane >= 8)  a += z8  * v;
        v = __shfl_up_sync(0xffffffffu, a, 16); if (lane >= 16) a += z16 * v;
        a += zl1 * carry;
        carry = __shfl_sync(0xffffffffu, a, 31);
        As[b] = a;
    }
    float A1022 = __shfl_sync(0xffffffffu, As[31], 30);

    float carryR = 0.0f;
    #pragma unroll
    for (int b = 31; b >= 0; b--) {
        float x = xs[b];
        float r = x, v;
        v = __shfl_down_sync(0xffffffffu, r, 1);  if (lane < 31) r += z1  * v;
        v = __shfl_down_sync(0xffffffffu, r, 2);  if (lane < 30) r += z2  * v;
        v = __shfl_down_sync(0xffffffffu, r, 4);  if (lane < 28) r += z4  * v;
        v = __shfl_down_sync(0xffffffffu, r, 8);  if (lane < 24) r += z8  * v;
        v = __shfl_down_sync(0xffffffffu, r, 16); if (lane < 16) r += z16 * v;
        r += zr * carryR;
        carryR = __shfl_sync(0xffffffffu, r, 0);
        float d = r - x;
        float t = As[b] + d;
        if (b == 31) t += zr * A1022;
        if (b == 0) {
            float B0 = __shfl_sync(0xffffffffu, d, 0);
            t += zl0 * B0;
        }
        orow[b*32 + lane] = __float2half_rn(SQ3 * t);
    }
}

// --- column prefilter: warp = 4 channels x 8 x -> coalesced fp16 store -------
__global__ void __launch_bounds__(256) colfilt_kernel() {
    int cl = threadIdx.x & 3;                  // channel within group
    int x  = blockIdx.x * 64 + (threadIdx.x >> 2);
    int g  = blockIdx.z;                       // channel group
    int c  = g*4 + cl;
    int ys = blockIdx.y * 32;
    const __half* base = g_tmp + c * HW + x;
    __half* ob = g_coefh + (size_t)g * 4 * HW + cl + 4 * (size_t)x;
    const float Zf  = (float)ZD;
    const float SQ3 = (float)((1.0-ZD)/(1.0+ZD));

    float A = 0.0f;
    #pragma unroll
    for (int j = 16; j >= 1; j--) {           // causal warm-up (mirror at top)
        int yy = ys - j; yy = yy < 0 ? -yy : yy;
        A = fmaf(Zf, A, __half2float(base[yy*Ww]));
    }
    float xs[32], As[32];
    #pragma unroll
    for (int j = 0; j < 32; j++) {
        float v = __half2float(base[(ys + j)*Ww]);
        A = fmaf(Zf, A, v);
        xs[j] = v; As[j] = A;
    }
    float R = 0.0f;
    #pragma unroll
    for (int j = 15; j >= 0; j--) {           // anticausal warm-up (mirror at bottom)
        int yy = ys + 32 + j; yy = yy > 1023 ? 2046 - yy : yy;
        R = fmaf(Zf, R, __half2float(base[yy*Ww]));
    }
    #pragma unroll
    for (int j = 31; j >= 0; j--) {
        ob[(size_t)(ys + j) * (4*Ww)] = __float2half_rn(SQ3 * fmaf(Zf, R, As[j]));
        R = fmaf(Zf, R, xs[j]);
    }
}

// fast weights for the image gather (loose tolerance path)
__device__ __forceinline__ void cubw_fast(float f, float* w) {
    float f2 = f*f;
    float f3 = f2*f;
    const float S = 1.0f/6.0f;
    w[0] = (1.0f - 3.0f*f + 3.0f*f2 - f3) * S;
    w[1] = (4.0f - 6.0f*f2 + 3.0f*f3) * S;
    w[2] = (1.0f + 3.0f*f + 3.0f*f2 - 3.0f*f3) * S;
    w[3] = f3 * S;
}

// --- monolithic eval: strict field + fp32 half4 gather + nearest mask --------
// __ldcs on mask (read-once stream), __stcs on out (write-once stream):
// keeps L2 resident for the 32MB coefficient working set.
__global__ void __launch_bounds__(256, 5) eval_kernel(const float* __restrict__ mask,
                                                      float* __restrict__ out) {
    int x = blockIdx.x * 256 + threadIdx.x;
    int y = blockIdx.y;

    float sy, sx;
    dense_field(x, y, sy, sx);
    bool valid = (sy >= 0.0f) && (sy <= 1023.0f) && (sx >= 0.0f) && (sx <= 1023.0f);
    int oidx = y*Ww + x;

    if (!valid) {
        #pragma unroll
        for (int c = 0; c < 2*Cc; c++)
            __stcs(out + c*HW + oidx, 0.0f);
        return;
    }

    // ---- mask: nearest (half-even), verified --------------------------------
    {
        int ny = (int)rintf(sy); ny = ny < 0 ? 0 : (ny > 1023 ? 1023 : ny);
        int nx = (int)rintf(sx); nx = nx < 0 ? 0 : (nx > 1023 ? 1023 : nx);
        int midx = ny*Ww + nx;
        #pragma unroll
        for (int c = 0; c < Cc; c++)
            __stcs(out + (Cc + c)*HW + oidx, __ldcs(mask + c*HW + midx));
    }

    // ---- image: fp16 channel-interleaved cubic gather, fp32 dot -------------
    float fs = floorf(sy); int iy = (int)fs; float fy = sy - fs;
    float gs = floorf(sx); int ix = (int)gs; float fx = sx - gs;
    float Wy[4], Wx[4];
    cubw_fast(fy, Wy); cubw_fast(fx, Wx);
    int ry[4], rx[4];
    #pragma unroll
    for (int a = 0; a < 4; a++) ry[a] = refl1024(iy + a - 1) * Ww;
    #pragma unroll
    for (int b = 0; b < 4; b++) rx[b] = refl1024(ix + b - 1);

    #pragma unroll
    for (int g = 0; g < 4; g++) {
        const __half* Ph = g_coefh + (size_t)g * 4 * HW;
        float s0 = 0.0f, s1 = 0.0f, s2 = 0.0f, s3 = 0.0f;
        #pragma unroll
        for (int a = 0; a < 4; a++) {
            const __half* pr = Ph + 4 * (size_t)ry[a];
            float2 f0[4], f1[4];
            #pragma unroll
            for (int b = 0; b < 4; b++) {
                uint2 v = __ldg((const uint2*)(pr + 4*rx[b]));
                __half2 h01 = *reinterpret_cast<__half2*>(&v.x);
                __half2 h23 = *reinterpret_cast<__half2*>(&v.y);
                f0[b] = __half22float2(h01);
                f1[b] = __half22float2(h23);
            }
            float r0 = Wx[0]*f0[0].x; r0 = fmaf(Wx[1], f0[1].x, r0);
            r0 = fmaf(Wx[2], f0[2].x, r0); r0 = fmaf(Wx[3], f0[3].x, r0);
            float r1 = Wx[0]*f0[0].y; r1 = fmaf(Wx[1], f0[1].y, r1);
            r1 = fmaf(Wx[2], f0[2].y, r1); r1 = fmaf(Wx[3], f0[3].y, r1);
            float r2 = Wx[0]*f1[0].x; r2 = fmaf(Wx[1], f1[1].x, r2);
            r2 = fmaf(Wx[2], f1[2].x, r2); r2 = fmaf(Wx[3], f1[3].x, r2);
            float r3 = Wx[0]*f1[0].y; r3 = fmaf(Wx[1], f1[1].y, r3);
            r3 = fmaf(Wx[2], f1[2].y, r3); r3 = fmaf(Wx[3], f1[3].y, r3);
            s0 = fmaf(Wy[a], r0, s0);
            s1 = fmaf(Wy[a], r1, s1);
            s2 = fmaf(Wy[a], r2, s2);
            s3 = fmaf(Wy[a], r3, s3);
        }
        __stcs(out + (g*4 + 0)*HW + oidx, s0);
        __stcs(out + (g*4 + 1)*HW + oidx, s1);
        __stcs(out + (g*4 + 2)*HW + oidx, s2);
        __stcs(out + (g*4 + 3)*HW + oidx, s3);
    }
}

extern "C" void kernel_launch(void* const* d_in, const int* in_sizes, int n_in,
                              void* d_out, int out_size) {
    const float* image = (const float*)d_in[0];
    const float* mask  = (const float*)d_in[1];
    const float* disp  = (const float*)d_in[2];
    float* out = (float*)d_out;

    table_kernel<<<4, 256>>>(disp);
    rowfilt_kernel<<<2048, 256>>>(image);
    colfilt_kernel<<<dim3(16, 32, 4), 256>>>();
    eval_kernel<<<dim3(4, 1024), 256>>>(mask, out);
}

// round 14
// speedup vs baseline: 1.4740x; 1.4740x over previous
#include <cuda_runtime.h>
#include <cuda_fp16.h>
#include <math.h>

#define Hh 1024
#define Ww 1024
#define Cc 16
#define HW (1024*1024)

#define ZD (-0.26794919243112270647)   // sqrt(3) - 2

static __device__ __half g_tmp[Cc*HW];     // row-filtered image fp16 (plane layout)
static __device__ __half g_coefh[Cc*HW];   // prefiltered coefs fp16, [group][y][x][4ch]
static __device__ float  g_zp[132];        // z^i, i=0..128
static __device__ float4 g_wy4[1024];      // strict cubic weights per coordinate
static __device__ int    g_myp[1024];      // packed mirrored indices (2 bits x 4)
static __device__ float  g_R[6*1024];      // folded x-dir displacement rows [ch*3+j][x]

// --- exact reference 3-point spline_filter1d (horizon = 3), eager-mode fp32 --
__device__ __forceinline__ void filt3(float v0, float v1, float v2, float* o) {
    const float Zf    = (float)ZD;
    const float Z2f   = (float)(ZD*ZD);
    const float GAIN  = 6.0f;                      // (1-z)(1-1/z) = 6 exactly
    const float LASTC = (float)(ZD/(ZD*ZD-1.0));
    float c0 = __fmul_rn(v0, GAIN);
    float c1 = __fmul_rn(v1, GAIN);
    float c2 = __fmul_rn(v2, GAIN);
    float cp0 = c0;
    cp0 = __fmaf_rn(Zf,  c1, cp0);
    cp0 = __fmaf_rn(Z2f, c2, cp0);
    float cp1 = __fadd_rn(c1, __fmul_rn(Zf, cp0));
    float cp2 = __fadd_rn(c2, __fmul_rn(Zf, cp1));
    float last = __fmul_rn(LASTC, __fadd_rn(cp2, __fmul_rn(Zf, cp1)));
    float o1 = __fmul_rn(Zf, __fsub_rn(last, cp1));
    float o0 = __fmul_rn(Zf, __fsub_rn(o1,  cp0));
    o[0] = o0; o[1] = o1; o[2] = last;
}

// --- strict (eager-jax) cubic weights ----------------------------------------
__device__ __forceinline__ void cubw_strict(float f, float* w) {
    float f2 = __fmul_rn(f, f);
    float f3 = __fmul_rn(f2, f);
    float t = __fsub_rn(1.0f, __fmul_rn(3.0f, f));
    t = __fadd_rn(t, __fmul_rn(3.0f, f2));
    t = __fsub_rn(t, f3);
    w[0] = __fdiv_rn(t, 6.0f);
    t = __fsub_rn(4.0f, __fmul_rn(6.0f, f2));
    t = __fadd_rn(t, __fmul_rn(3.0f, f3));
    w[1] = __fdiv_rn(t, 6.0f);
    t = __fadd_rn(1.0f, __fmul_rn(3.0f, f));
    t = __fadd_rn(t, __fmul_rn(3.0f, f2));
    t = __fsub_rn(t, __fmul_rn(3.0f, f3));
    w[2] = __fdiv_rn(t, 6.0f);
    w[3] = __fdiv_rn(f3, 6.0f);
}

__device__ __forceinline__ int mir3(int i) {        // mirror, n=3 (period 4)
    int m = i < 0 ? -i : i;
    m &= 3;
    return m > 2 ? 4 - m : m;
}
__device__ __forceinline__ int refl1024(int i) {    // mirror, n=1024 (small excursions)
    return i < 0 ? -i : (i > 1023 ? 2046 - i : i);
}

// --- fused setup + tables + z-power table ------------------------------------
__global__ void table_kernel(const float* __restrict__ disp) {
    __shared__ float dcoef[18];
    if (threadIdx.x == 0) {
        if (blockIdx.x == 0) {
            double zp = 1.0;
            for (int i = 0; i <= 128; i++) { g_zp[i] = (float)zp; zp *= ZD; }
        }
        float d[2][3][3];
        for (int ch = 0; ch < 2; ch++)
            for (int i = 0; i < 3; i++)
                for (int j = 0; j < 3; j++)
                    d[ch][i][j] = __fmul_rn(disp[ch*9 + i*3 + j], 10.0f);   // SIGMA
        for (int ch = 0; ch < 2; ch++)
            for (int j = 0; j < 3; j++) {
                float o[3];
                filt3(d[ch][0][j], d[ch][1][j], d[ch][2][j], o);
                d[ch][0][j] = o[0]; d[ch][1][j] = o[1]; d[ch][2][j] = o[2];
            }
        for (int ch = 0; ch < 2; ch++)
            for (int i = 0; i < 3; i++) {
                float o[3];
                filt3(d[ch][i][0], d[ch][i][1], d[ch][i][2], o);
                dcoef[ch*9 + i*3 + 0] = o[0];
                dcoef[ch*9 + i*3 + 1] = o[1];
                dcoef[ch*9 + i*3 + 2] = o[2];
            }
    }
    __syncthreads();

    int i = blockIdx.x * 256 + threadIdx.x;         // coordinate 0..1023
    const float SCL = (float)(2.0/1023.0);
    float u = __fmul_rn((float)i, SCL);
    float fl = floorf(u); int i0 = (int)fl;
    float f = __fsub_rn(u, fl);
    float w[4];
    cubw_strict(f, w);
    int m[4];
    #pragma unroll
    for (int b = 0; b < 4; b++) m[b] = mir3(i0 + b - 1);
    g_wy4[i] = make_float4(w[0], w[1], w[2], w[3]);
    g_myp[i] = m[0] | (m[1] << 2) | (m[2] << 4) | (m[3] << 6);
    #pragma unroll
    for (int ch = 0; ch < 2; ch++)
        #pragma unroll
        for (int j = 0; j < 3; j++) {
            float r = 0.0f;
            #pragma unroll
            for (int b = 0; b < 4; b++)
                r = __fadd_rn(r, __fmul_rn(w[b], dcoef[ch*9 + j*3 + m[b]]));
            g_R[(ch*3 + j)*1024 + i] = r;
        }
}

// --- strict dense field at (y, x) — verified bit-identical to reference ------
__device__ __forceinline__ void dense_field(int x, int y, float& sy, float& sx) {
    float4 wy = g_wy4[y];
    int mp = g_myp[y];
    const float* Rx = g_R + x;
    float d0 = 0.0f, d1 = 0.0f;
    int j;
    j = mp & 3;
    d0 = __fadd_rn(d0, __fmul_rn(wy.x, __ldg(Rx + j*1024)));
    d1 = __fadd_rn(d1, __fmul_rn(wy.x, __ldg(Rx + (3+j)*1024)));
    j = (mp >> 2) & 3;
    d0 = __fadd_rn(d0, __fmul_rn(wy.y, __ldg(Rx + j*1024)));
    d1 = __fadd_rn(d1, __fmul_rn(wy.y, __ldg(Rx + (3+j)*1024)));
    j = (mp >> 4) & 3;
    d0 = __fadd_rn(d0, __fmul_rn(wy.z, __ldg(Rx + j*1024)));
    d1 = __fadd_rn(d1, __fmul_rn(wy.z, __ldg(Rx + (3+j)*1024)));
    j = (mp >> 6) & 3;
    d0 = __fadd_rn(d0, __fmul_rn(wy.w, __ldg(Rx + j*1024)));
    d1 = __fadd_rn(d1, __fmul_rn(wy.w, __ldg(Rx + (3+j)*1024)));
    sy = __fadd_rn((float)y, d0);
    sx = __fadd_rn((float)x, d1);
}

// --- row prefilter: block-serial scan, lane owns 4 consecutive elements ------
// 128-element blocks: 4-step serial IIR per lane + 5-step Kogge-Stone (weights
// z^4..z^64). Mirror corrections: z^(1024-e)*A1022 (right), z^e*B0 (left).
__global__ void __launch_bounds__(256) rowfilt_kernel(const float* __restrict__ img) {
    int warp = blockIdx.x * 8 + (threadIdx.x >> 5);   // row id: c*1024 + y
    int lane = threadIdx.x & 31;
    const float4* row4 = (const float4*)(img + warp * Ww);
    __half* orow = g_tmp + warp * Ww;

    const float z1  = (float)ZD;
    const float z2f = (float)(ZD*ZD);
    const float z3f = (float)(ZD*ZD*ZD);
    const float z4f = (float)(ZD*ZD*ZD*ZD);
    const float z8f  = z4f*z4f;
    const float z16f = z8f*z8f;
    const float z32f = z16f*z16f;
    const float z64f = z32f*z32f;
    const float SQ3 = (float)((1.0-ZD)/(1.0+ZD));   // sqrt(3)

    float zcw = g_zp[4*lane];          // z^(4*lane): causal block-carry weight
    float zaw = g_zp[124 - 4*lane];    // anticausal block-carry weight

    float xs[32], As[32];
    float carry = 0.0f;
    float A1022 = 0.0f;

    // ---- causal pass (forward) ----
    #pragma unroll
    for (int blk = 0; blk < 8; blk++) {
        float4 x = __ldg(row4 + blk*32 + lane);
        float a0 = x.x;
        float a1 = fmaf(z1, a0, x.y);
        float a2 = fmaf(z1, a1, x.z);
        float a3 = fmaf(z1, a2, x.w);
        float s = a3, v;
        v = __shfl_up_sync(0xffffffffu, s, 1);  if (lane >= 1)  s = fmaf(z4f,  v, s);
        v = __shfl_up_sync(0xffffffffu, s, 2);  if (lane >= 2)  s = fmaf(z8f,  v, s);
        v = __shfl_up_sync(0xffffffffu, s, 4);  if (lane >= 4)  s = fmaf(z16f, v, s);
        v = __shfl_up_sync(0xffffffffu, s, 8);  if (lane >= 8)  s = fmaf(z32f, v, s);
        v = __shfl_up_sync(0xffffffffu, s, 16); if (lane >= 16) s = fmaf(z64f, v, s);
        float seg = __shfl_up_sync(0xffffffffu, s, 1);
        seg = (lane == 0 ? 0.0f : seg) + zcw * carry;
        a0 = fmaf(z1,  seg, a0);
        a1 = fmaf(z2f, seg, a1);
        a2 = fmaf(z3f, seg, a2);
        a3 = fmaf(z4f, seg, a3);
        xs[blk*4+0] = x.x; xs[blk*4+1] = x.y; xs[blk*4+2] = x.z; xs[blk*4+3] = x.w;
        As[blk*4+0] = a0;  As[blk*4+1] = a1;  As[blk*4+2] = a2;  As[blk*4+3] = a3;
        carry = __shfl_sync(0xffffffffu, a3, 31);
        if (blk == 7) A1022 = __shfl_sync(0xffffffffu, a2, 31);  // state at e=1022
    }

    // ---- anticausal pass (backward) + combine + store ----
    float carryR = 0.0f;
    #pragma unroll
    for (int blk = 7; blk >= 0; blk--) {
        float x0 = xs[blk*4+0], x1 = xs[blk*4+1], x2 = xs[blk*4+2], x3 = xs[blk*4+3];
        float r3 = x3;
        float r2 = fmaf(z1, r3, x2);
        float r1 = fmaf(z1, r2, x1);
        float r0 = fmaf(z1, r1, x0);
        float s = r0, v;
        v = __shfl_down_sync(0xffffffffu, s, 1);  if (lane < 31) s = fmaf(z4f,  v, s);
        v = __shfl_down_sync(0xffffffffu, s, 2);  if (lane < 30) s = fmaf(z8f,  v, s);
        v = __shfl_down_sync(0xffffffffu, s, 4);  if (lane < 28) s = fmaf(z16f, v, s);
        v = __shfl_down_sync(0xffffffffu, s, 8);  if (lane < 24) s = fmaf(z32f, v, s);
        v = __shfl_down_sync(0xffffffffu, s, 16); if (lane < 16) s = fmaf(z64f, v, s);
        float segR = __shfl_down_sync(0xffffffffu, s, 1);
        segR = (lane == 31 ? 0.0f : segR) + zaw * carryR;
        r0 = fmaf(z4f, segR, r0);
        r1 = fmaf(z3f, segR, r1);
        r2 = fmaf(z2f, segR, r2);
        r3 = fmaf(z1,  segR, r3);
        carryR = __shfl_sync(0xffffffffu, r0, 0);

        float t0 = As[blk*4+0] + (r0 - x0);
        float t1 = As[blk*4+1] + (r1 - x1);
        float t2 = As[blk*4+2] + (r2 - x2);
        float t3 = As[blk*4+3] + (r3 - x3);
        if (blk == 7) {                       // right mirror: z^(1024-e) * A1022
            int base = 128 - 4*lane;          // e = 896 + 4*lane + j
            t0 = fmaf(g_zp[base    ], A1022, t0);
            t1 = fmaf(g_zp[base - 1], A1022, t1);
            t2 = fmaf(g_zp[base - 2], A1022, t2);
            t3 = fmaf(g_zp[base - 3], A1022, t3);
        }
        if (blk == 0) {                       // left mirror: z^e * B0
            float B0 = __shfl_sync(0xffffffffu, r0 - x0, 0);
            int base = 4*lane;
            t0 = fmaf(g_zp[base    ], B0, t0);
            t1 = fmaf(g_zp[base + 1], B0, t1);
            t2 = fmaf(g_zp[base + 2], B0, t2);
            t3 = fmaf(g_zp[base + 3], B0, t3);
        }
        __half2 h01 = __halves2half2(__float2half_rn(SQ3*t0), __float2half_rn(SQ3*t1));
        __half2 h23 = __halves2half2(__float2half_rn(SQ3*t2), __float2half_rn(SQ3*t3));
        __half2* dst = (__half2*)(orow + blk*128 + lane*4);
        dst[0] = h01;
        dst[1] = h23;
    }
}

// --- column prefilter: warp = 4 channels x 8 x -> coalesced fp16 store -------
__global__ void __launch_bounds__(256) colfilt_kernel() {
    int cl = threadIdx.x & 3;                  // channel within group
    int x  = blockIdx.x * 64 + (threadIdx.x >> 2);
    int g  = blockIdx.z;                       // channel group
    int c  = g*4 + cl;
    int ys = blockIdx.y * 32;
    const __half* base = g_tmp + c * HW + x;
    __half* ob = g_coefh + (size_t)g * 4 * HW + cl + 4 * (size_t)x;
    const float Zf  = (float)ZD;
    const float SQ3 = (float)((1.0-ZD)/(1.0+ZD));

    float A = 0.0f;
    #pragma unroll
    for (int j = 16; j >= 1; j--) {           // causal warm-up (mirror at top)
        int yy = ys - j; yy = yy < 0 ? -yy : yy;
        A = fmaf(Zf, A, __half2float(base[yy*Ww]));
    }
    float xs[32], As[32];
    #pragma unroll
    for (int j = 0; j < 32; j++) {
        float v = __half2float(base[(ys + j)*Ww]);
        A = fmaf(Zf, A, v);
        xs[j] = v; As[j] = A;
    }
    float R = 0.0f;
    #pragma unroll
    for (int j = 15; j >= 0; j--) {           // anticausal warm-up (mirror at bottom)
        int yy = ys + 32 + j; yy = yy > 1023 ? 2046 - yy : yy;
        R = fmaf(Zf, R, __half2float(base[yy*Ww]));
    }
    #pragma unroll
    for (int j = 31; j >= 0; j--) {
        ob[(size_t)(ys + j) * (4*Ww)] = __float2half_rn(SQ3 * fmaf(Zf, R, As[j]));
        R = fmaf(Zf, R, xs[j]);
    }
}

// fast weights for the image gather (loose tolerance path)
__device__ __forceinline__ void cubw_fast(float f, float* w) {
    float f2 = f*f;
    float f3 = f2*f;
    const float S = 1.0f/6.0f;
    w[0] = (1.0f - 3.0f*f + 3.0f*f2 - f3) * S;
    w[1] = (4.0f - 6.0f*f2 + 3.0f*f3) * S;
    w[2] = (1.0f + 3.0f*f + 3.0f*f2 - 3.0f*f3) * S;
    w[3] = f3 * S;
}

// --- monolithic eval (round-11 verified, 57.4us): strict field + fp16 gather --
__global__ void __launch_bounds__(256, 4) eval_kernel(const float* __restrict__ mask,
                                                      float* __restrict__ out) {
    int x = blockIdx.x * 256 + threadIdx.x;
    int y = blockIdx.y;

    float sy, sx;
    dense_field(x, y, sy, sx);
    bool valid = (sy >= 0.0f) && (sy <= 1023.0f) && (sx >= 0.0f) && (sx <= 1023.0f);
    int oidx = y*Ww + x;

    if (!valid) {
        #pragma unroll
        for (int c = 0; c < 2*Cc; c++)
            out[c*HW + oidx] = 0.0f;
        return;
    }

    // ---- mask: nearest (half-even), verified --------------------------------
    {
        int ny = (int)rintf(sy); ny = ny < 0 ? 0 : (ny > 1023 ? 1023 : ny);
        int nx = (int)rintf(sx); nx = nx < 0 ? 0 : (nx > 1023 ? 1023 : nx);
        int midx = ny*Ww + nx;
        #pragma unroll
        for (int c = 0; c < Cc; c++)
            out[(Cc + c)*HW + oidx] = __ldg(mask + c*HW + midx);
    }

    // ---- image: fp16 channel-interleaved cubic gather, fp32 dot -------------
    float fs = floorf(sy); int iy = (int)fs; float fy = sy - fs;
    float gs = floorf(sx); int ix = (int)gs; float fx = sx - gs;
    float Wy[4], Wx[4];
    cubw_fast(fy, Wy); cubw_fast(fx, Wx);
    int ry[4], rx[4];
    #pragma unroll
    for (int a = 0; a < 4; a++) ry[a] = refl1024(iy + a - 1) * Ww;
    #pragma unroll
    for (int b = 0; b < 4; b++) rx[b] = refl1024(ix + b - 1);

    #pragma unroll
    for (int g = 0; g < 4; g++) {
        const __half* Ph = g_coefh + (size_t)g * 4 * HW;
        float s0 = 0.0f, s1 = 0.0f, s2 = 0.0f, s3 = 0.0f;
        #pragma unroll
        for (int a = 0; a < 4; a++) {
            const __half* pr = Ph + 4 * (size_t)ry[a];
            float2 f0[4], f1[4];
            #pragma unroll
            for (int b = 0; b < 4; b++) {
                uint2 v = __ldg((const uint2*)(pr + 4*rx[b]));
                __half2 h01 = *reinterpret_cast<__half2*>(&v.x);
                __half2 h23 = *reinterpret_cast<__half2*>(&v.y);
                f0[b] = __half22float2(h01);
                f1[b] = __half22float2(h23);
            }
            float r0 = Wx[0]*f0[0].x; r0 = fmaf(Wx[1], f0[1].x, r0);
            r0 = fmaf(Wx[2], f0[2].x, r0); r0 = fmaf(Wx[3], f0[3].x, r0);
            float r1 = Wx[0]*f0[0].y; r1 = fmaf(Wx[1], f0[1].y, r1);
            r1 = fmaf(Wx[2], f0[2].y, r1); r1 = fmaf(Wx[3], f0[3].y, r1);
            float r2 = Wx[0]*f1[0].x; r2 = fmaf(Wx[1], f1[1].x, r2);
            r2 = fmaf(Wx[2], f1[2].x, r2); r2 = fmaf(Wx[3], f1[3].x, r2);
            float r3 = Wx[0]*f1[0].y; r3 = fmaf(Wx[1], f1[1].y, r3);
            r3 = fmaf(Wx[2], f1[2].y, r3); r3 = fmaf(Wx[3], f1[3].y, r3);
            s0 = fmaf(Wy[a], r0, s0);
            s1 = fmaf(Wy[a], r1, s1);
            s2 = fmaf(Wy[a], r2, s2);
            s3 = fmaf(Wy[a], r3, s3);
        }
        out[(g*4 + 0)*HW + oidx] = s0;
        out[(g*4 + 1)*HW + oidx] = s1;
        out[(g*4 + 2)*HW + oidx] = s2;
        out[(g*4 + 3)*HW + oidx] = s3;
    }
}

extern "C" void kernel_launch(void* const* d_in, const int* in_sizes, int n_in,
                              void* d_out, int out_size) {
    const float* image = (const float*)d_in[0];
    const float* mask  = (const float*)d_in[1];
    const float* disp  = (const float*)d_in[2];
    float* out = (float*)d_out;

    table_kernel<<<4, 256>>>(disp);
    rowfilt_kernel<<<2048, 256>>>(image);
    colfilt_kernel<<<dim3(16, 32, 4), 256>>>();
    eval_kernel<<<dim3(4, 1024), 256>>>(mask, out);
}

// round 15
// speedup vs baseline: 1.5253x; 1.0349x over previous
#include <cuda_runtime.h>
#include <cuda_fp16.h>
#include <math.h>

#define Hh 1024
#define Ww 1024
#define Cc 16
#define HW (1024*1024)

#define ZD (-0.26794919243112270647)   // sqrt(3) - 2

static __device__ __half g_tmp[Cc*HW];     // row-filtered image fp16 (plane layout)
static __device__ __half g_coefh[Cc*HW];   // prefiltered coefs fp16, [group][y][x][4ch]
static __device__ float4 g_wy4[1024];      // strict cubic weights per coordinate
static __device__ int    g_myp[1024];      // packed mirrored indices (2 bits x 4)
static __device__ float  g_R[6*1024];      // folded x-dir displacement rows [ch*3+j][x]

// --- exact reference 3-point spline_filter1d (horizon = 3), eager-mode fp32 --
__device__ __forceinline__ void filt3(float v0, float v1, float v2, float* o) {
    const float Zf    = (float)ZD;
    const float Z2f   = (float)(ZD*ZD);
    const float GAIN  = 6.0f;                      // (1-z)(1-1/z) = 6 exactly
    const float LASTC = (float)(ZD/(ZD*ZD-1.0));
    float c0 = __fmul_rn(v0, GAIN);
    float c1 = __fmul_rn(v1, GAIN);
    float c2 = __fmul_rn(v2, GAIN);
    float cp0 = c0;
    cp0 = __fmaf_rn(Zf,  c1, cp0);
    cp0 = __fmaf_rn(Z2f, c2, cp0);
    float cp1 = __fadd_rn(c1, __fmul_rn(Zf, cp0));
    float cp2 = __fadd_rn(c2, __fmul_rn(Zf, cp1));
    float last = __fmul_rn(LASTC, __fadd_rn(cp2, __fmul_rn(Zf, cp1)));
    float o1 = __fmul_rn(Zf, __fsub_rn(last, cp1));
    float o0 = __fmul_rn(Zf, __fsub_rn(o1,  cp0));
    o[0] = o0; o[1] = o1; o[2] = last;
}

// --- strict (eager-jax) cubic weights ----------------------------------------
__device__ __forceinline__ void cubw_strict(float f, float* w) {
    float f2 = __fmul_rn(f, f);
    float f3 = __fmul_rn(f2, f);
    float t = __fsub_rn(1.0f, __fmul_rn(3.0f, f));
    t = __fadd_rn(t, __fmul_rn(3.0f, f2));
    t = __fsub_rn(t, f3);
    w[0] = __fdiv_rn(t, 6.0f);
    t = __fsub_rn(4.0f, __fmul_rn(6.0f, f2));
    t = __fadd_rn(t, __fmul_rn(3.0f, f3));
    w[1] = __fdiv_rn(t, 6.0f);
    t = __fadd_rn(1.0f, __fmul_rn(3.0f, f));
    t = __fadd_rn(t, __fmul_rn(3.0f, f2));
    t = __fsub_rn(t, __fmul_rn(3.0f, f3));
    w[2] = __fdiv_rn(t, 6.0f);
    w[3] = __fdiv_rn(f3, 6.0f);
}

__device__ __forceinline__ int mir3(int i) {        // mirror, n=3 (period 4)
    int m = i < 0 ? -i : i;
    m &= 3;
    return m > 2 ? 4 - m : m;
}
__device__ __forceinline__ int refl1024(int i) {    // mirror, n=1024 (small excursions)
    return i < 0 ? -i : (i > 1023 ? 2046 - i : i);
}

// --- fused setup + strict tables (no serial z-power loop anymore) ------------
__global__ void table_kernel(const float* __restrict__ disp) {
    __shared__ float dcoef[18];
    if (threadIdx.x == 0) {
        float d[2][3][3];
        for (int ch = 0; ch < 2; ch++)
            for (int i = 0; i < 3; i++)
                for (int j = 0; j < 3; j++)
                    d[ch][i][j] = __fmul_rn(disp[ch*9 + i*3 + j], 10.0f);   // SIGMA
        for (int ch = 0; ch < 2; ch++)
            for (int j = 0; j < 3; j++) {
                float o[3];
                filt3(d[ch][0][j], d[ch][1][j], d[ch][2][j], o);
                d[ch][0][j] = o[0]; d[ch][1][j] = o[1]; d[ch][2][j] = o[2];
            }
        for (int ch = 0; ch < 2; ch++)
            for (int i = 0; i < 3; i++) {
                float o[3];
                filt3(d[ch][i][0], d[ch][i][1], d[ch][i][2], o);
                dcoef[ch*9 + i*3 + 0] = o[0];
                dcoef[ch*9 + i*3 + 1] = o[1];
                dcoef[ch*9 + i*3 + 2] = o[2];
            }
    }
    __syncthreads();

    int i = blockIdx.x * 256 + threadIdx.x;         // coordinate 0..1023
    const float SCL = (float)(2.0/1023.0);
    float u = __fmul_rn((float)i, SCL);
    float fl = floorf(u); int i0 = (int)fl;
    float f = __fsub_rn(u, fl);
    float w[4];
    cubw_strict(f, w);
    int m[4];
    #pragma unroll
    for (int b = 0; b < 4; b++) m[b] = mir3(i0 + b - 1);
    g_wy4[i] = make_float4(w[0], w[1], w[2], w[3]);
    g_myp[i] = m[0] | (m[1] << 2) | (m[2] << 4) | (m[3] << 6);
    #pragma unroll
    for (int ch = 0; ch < 2; ch++)
        #pragma unroll
        for (int j = 0; j < 3; j++) {
            float r = 0.0f;
            #pragma unroll
            for (int b = 0; b < 4; b++)
                r = __fadd_rn(r, __fmul_rn(w[b], dcoef[ch*9 + j*3 + m[b]]));
            g_R[(ch*3 + j)*1024 + i] = r;
        }
}

// --- strict dense field at (y, x) — verified bit-identical to reference ------
__device__ __forceinline__ void dense_field(int x, int y, float& sy, float& sx) {
    float4 wy = g_wy4[y];
    int mp = g_myp[y];
    const float* Rx = g_R + x;
    float d0 = 0.0f, d1 = 0.0f;
    int j;
    j = mp & 3;
    d0 = __fadd_rn(d0, __fmul_rn(wy.x, __ldg(Rx + j*1024)));
    d1 = __fadd_rn(d1, __fmul_rn(wy.x, __ldg(Rx + (3+j)*1024)));
    j = (mp >> 2) & 3;
    d0 = __fadd_rn(d0, __fmul_rn(wy.y, __ldg(Rx + j*1024)));
    d1 = __fadd_rn(d1, __fmul_rn(wy.y, __ldg(Rx + (3+j)*1024)));
    j = (mp >> 4) & 3;
    d0 = __fadd_rn(d0, __fmul_rn(wy.z, __ldg(Rx + j*1024)));
    d1 = __fadd_rn(d1, __fmul_rn(wy.z, __ldg(Rx + (3+j)*1024)));
    j = (mp >> 6) & 3;
    d0 = __fadd_rn(d0, __fmul_rn(wy.w, __ldg(Rx + j*1024)));
    d1 = __fadd_rn(d1, __fmul_rn(wy.w, __ldg(Rx + (3+j)*1024)));
    sy = __fadd_rn((float)y, d0);
    sx = __fadd_rn((float)x, d1);
}

// fp32 z^e via binary-power product (e in 0..127; z^128 flushed to 0)
__device__ __forceinline__ float zpowf(int e) {
    const float zb1  = (float)ZD;
    const float zb2  = zb1*zb1;
    const float zb4  = zb2*zb2;
    const float zb8  = zb4*zb4;
    const float zb16 = zb8*zb8;
    const float zb32 = zb16*zb16;
    const float zb64 = zb32*zb32;
    float r = 1.0f;
    if (e & 1)  r *= zb1;
    if (e & 2)  r *= zb2;
    if (e & 4)  r *= zb4;
    if (e & 8)  r *= zb8;
    if (e & 16) r *= zb16;
    if (e & 32) r *= zb32;
    if (e & 64) r *= zb64;
    if (e & 128) r = 0.0f;
    return r;
}

// --- row prefilter: block-serial scan, lane owns 4 consecutive elements ------
// 128-element blocks: 4-step serial IIR per lane + 5-step Kogge-Stone.
// Self-contained z-powers (no table dependency).
__global__ void __launch_bounds__(256) rowfilt_kernel(const float* __restrict__ img) {
    int warp = blockIdx.x * 8 + (threadIdx.x >> 5);   // row id: c*1024 + y
    int lane = threadIdx.x & 31;
    const float4* row4 = (const float4*)(img + warp * Ww);
    __half* orow = g_tmp + warp * Ww;

    const float z1  = (float)ZD;
    const float z2f = (float)(ZD*ZD);
    const float z3f = (float)(ZD*ZD*ZD);
    const float z4f = (float)(ZD*ZD*ZD*ZD);
    const float z8f  = z4f*z4f;
    const float z16f = z8f*z8f;
    const float z32f = z16f*z16f;
    const float z64f = z32f*z32f;
    const float SQ3 = (float)((1.0-ZD)/(1.0+ZD));   // sqrt(3)

    float zcw = zpowf(4*lane);          // z^(4*lane): causal block-carry weight
    float zaw = zpowf(124 - 4*lane);    // anticausal block-carry weight

    float xs[32], As[32];
    float carry = 0.0f;
    float A1022 = 0.0f;

    // ---- causal pass (forward) ----
    #pragma unroll
    for (int blk = 0; blk < 8; blk++) {
        float4 x = __ldg(row4 + blk*32 + lane);
        float a0 = x.x;
        float a1 = fmaf(z1, a0, x.y);
        float a2 = fmaf(z1, a1, x.z);
        float a3 = fmaf(z1, a2, x.w);
        float s = a3, v;
        v = __shfl_up_sync(0xffffffffu, s, 1);  if (lane >= 1)  s = fmaf(z4f,  v, s);
        v = __shfl_up_sync(0xffffffffu, s, 2);  if (lane >= 2)  s = fmaf(z8f,  v, s);
        v = __shfl_up_sync(0xffffffffu, s, 4);  if (lane >= 4)  s = fmaf(z16f, v, s);
        v = __shfl_up_sync(0xffffffffu, s, 8);  if (lane >= 8)  s = fmaf(z32f, v, s);
        v = __shfl_up_sync(0xffffffffu, s, 16); if (lane >= 16) s = fmaf(z64f, v, s);
        float seg = __shfl_up_sync(0xffffffffu, s, 1);
        seg = (lane == 0 ? 0.0f : seg) + zcw * carry;
        a0 = fmaf(z1,  seg, a0);
        a1 = fmaf(z2f, seg, a1);
        a2 = fmaf(z3f, seg, a2);
        a3 = fmaf(z4f, seg, a3);
        xs[blk*4+0] = x.x; xs[blk*4+1] = x.y; xs[blk*4+2] = x.z; xs[blk*4+3] = x.w;
        As[blk*4+0] = a0;  As[blk*4+1] = a1;  As[blk*4+2] = a2;  As[blk*4+3] = a3;
        carry = __shfl_sync(0xffffffffu, a3, 31);
        if (blk == 7) A1022 = __shfl_sync(0xffffffffu, a2, 31);  // state at e=1022
    }

    // ---- anticausal pass (backward) + combine + store ----
    float carryR = 0.0f;
    #pragma unroll
    for (int blk = 7; blk >= 0; blk--) {
        float x0 = xs[blk*4+0], x1 = xs[blk*4+1], x2 = xs[blk*4+2], x3 = xs[blk*4+3];
        float r3 = x3;
        float r2 = fmaf(z1, r3, x2);
        float r1 = fmaf(z1, r2, x1);
        float r0 = fmaf(z1, r1, x0);
        float s = r0, v;
        v = __shfl_down_sync(0xffffffffu, s, 1);  if (lane < 31) s = fmaf(z4f,  v, s);
        v = __shfl_down_sync(0xffffffffu, s, 2);  if (lane < 30) s = fmaf(z8f,  v, s);
        v = __shfl_down_sync(0xffffffffu, s, 4);  if (lane < 28) s = fmaf(z16f, v, s);
        v = __shfl_down_sync(0xffffffffu, s, 8);  if (lane < 24) s = fmaf(z32f, v, s);
        v = __shfl_down_sync(0xffffffffu, s, 16); if (lane < 16) s = fmaf(z64f, v, s);
        float segR = __shfl_down_sync(0xffffffffu, s, 1);
        segR = (lane == 31 ? 0.0f : segR) + zaw * carryR;
        r0 = fmaf(z4f, segR, r0);
        r1 = fmaf(z3f, segR, r1);
        r2 = fmaf(z2f, segR, r2);
        r3 = fmaf(z1,  segR, r3);
        carryR = __shfl_sync(0xffffffffu, r0, 0);

        float t0 = As[blk*4+0] + (r0 - x0);
        float t1 = As[blk*4+1] + (r1 - x1);
        float t2 = As[blk*4+2] + (r2 - x2);
        float t3 = As[blk*4+3] + (r3 - x3);
        if (blk == 7) {                       // right mirror: z^(1024-e) * A1022
            float w = zpowf(125 - 4*lane);    // z^(base-3), base = 128-4*lane
            t3 = fmaf(w, A1022, t3); w *= z1;
            t2 = fmaf(w, A1022, t2); w *= z1;
            t1 = fmaf(w, A1022, t1); w *= z1;
            t0 = fmaf(w, A1022, t0);
        }
        if (blk == 0) {                       // left mirror: z^e * B0
            float B0 = __shfl_sync(0xffffffffu, r0 - x0, 0);
            float w = zpowf(4*lane);
            t0 = fmaf(w, B0, t0); w *= z1;
            t1 = fmaf(w, B0, t1); w *= z1;
            t2 = fmaf(w, B0, t2); w *= z1;
            t3 = fmaf(w, B0, t3);
        }
        __half2 h01 = __halves2half2(__float2half_rn(SQ3*t0), __float2half_rn(SQ3*t1));
        __half2 h23 = __halves2half2(__float2half_rn(SQ3*t2), __float2half_rn(SQ3*t3));
        __half2* dst = (__half2*)(orow + blk*128 + lane*4);
        dst[0] = h01;
        dst[1] = h23;
    }
}

// --- column prefilter: warp = 4 channels x 8 x -> coalesced fp16 store -------
__global__ void __launch_bounds__(256) colfilt_kernel() {
    int cl = threadIdx.x & 3;                  // channel within group
    int x  = blockIdx.x * 64 + (threadIdx.x >> 2);
    int g  = blockIdx.z;                       // channel group
    int c  = g*4 + cl;
    int ys = blockIdx.y * 32;
    const __half* base = g_tmp + c * HW + x;
    __half* ob = g_coefh + (size_t)g * 4 * HW + cl + 4 * (size_t)x;
    const float Zf  = (float)ZD;
    const float SQ3 = (float)((1.0-ZD)/(1.0+ZD));

    float A = 0.0f;
    #pragma unroll
    for (int j = 16; j >= 1; j--) {           // causal warm-up (mirror at top)
        int yy = ys - j; yy = yy < 0 ? -yy : yy;
        A = fmaf(Zf, A, __half2float(base[yy*Ww]));
    }
    float xs[32], As[32];
    #pragma unroll
    for (int j = 0; j < 32; j++) {
        float v = __half2float(base[(ys + j)*Ww]);
        A = fmaf(Zf, A, v);
        xs[j] = v; As[j] = A;
    }
    float R = 0.0f;
    #pragma unroll
    for (int j = 15; j >= 0; j--) {           // anticausal warm-up (mirror at bottom)
        int yy = ys + 32 + j; yy = yy > 1023 ? 2046 - yy : yy;
        R = fmaf(Zf, R, __half2float(base[yy*Ww]));
    }
    #pragma unroll
    for (int j = 31; j >= 0; j--) {
        ob[(size_t)(ys + j) * (4*Ww)] = __float2half_rn(SQ3 * fmaf(Zf, R, As[j]));
        R = fmaf(Zf, R, xs[j]);
    }
}

// fast weights for the image gather (loose tolerance path)
__device__ __forceinline__ void cubw_fast(float f, float* w) {
    float f2 = f*f;
    float f3 = f2*f;
    const float S = 1.0f/6.0f;
    w[0] = (1.0f - 3.0f*f + 3.0f*f2 - f3) * S;
    w[1] = (4.0f - 6.0f*f2 + 3.0f*f3) * S;
    w[2] = (1.0f + 3.0f*f + 3.0f*f2 - 3.0f*f3) * S;
    w[3] = f3 * S;
}

// --- monolithic eval: strict field + fp16 gather; __stcs on the out stream ---
// (out is write-once 128MB: evict-first keeps L2 resident for 32MB coef set)
__global__ void __launch_bounds__(256, 4) eval_kernel(const float* __restrict__ mask,
                                                      float* __restrict__ out) {
    int x = blockIdx.x * 256 + threadIdx.x;
    int y = blockIdx.y;

    float sy, sx;
    dense_field(x, y, sy, sx);
    bool valid = (sy >= 0.0f) && (sy <= 1023.0f) && (sx >= 0.0f) && (sx <= 1023.0f);
    int oidx = y*Ww + x;

    if (!valid) {
        #pragma unroll
        for (int c = 0; c < 2*Cc; c++)
            __stcs(out + c*HW + oidx, 0.0f);
        return;
    }

    // ---- mask: nearest (half-even), verified --------------------------------
    {
        int ny = (int)rintf(sy); ny = ny < 0 ? 0 : (ny > 1023 ? 1023 : ny);
        int nx = (int)rintf(sx); nx = nx < 0 ? 0 : (nx > 1023 ? 1023 : nx);
        int midx = ny*Ww + nx;
        #pragma unroll
        for (int c = 0; c < Cc; c++)
            __stcs(out + (Cc + c)*HW + oidx, __ldg(mask + c*HW + midx));
    }

    // ---- image: fp16 channel-interleaved cubic gather, fp32 dot -------------
    float fs = floorf(sy); int iy = (int)fs; float fy = sy - fs;
    float gs = floorf(sx); int ix = (int)gs; float fx = sx - gs;
    float Wy[4], Wx[4];
    cubw_fast(fy, Wy); cubw_fast(fx, Wx);
    int ry[4], rx[4];
    #pragma unroll
    for (int a = 0; a < 4; a++) ry[a] = refl1024(iy + a - 1) * Ww;
    #pragma unroll
    for (int b = 0; b < 4; b++) rx[b] = refl1024(ix + b - 1);

    #pragma unroll
    for (int g = 0; g < 4; g++) {
        const __half* Ph = g_coefh + (size_t)g * 4 * HW;
        float s0 = 0.0f, s1 = 0.0f, s2 = 0.0f, s3 = 0.0f;
        #pragma unroll
        for (int a = 0; a < 4; a++) {
            const __half* pr = Ph + 4 * (size_t)ry[a];
            float2 f0[4], f1[4];
            #pragma unroll
            for (int b = 0; b < 4; b++) {
                uint2 v = __ldg((const uint2*)(pr + 4*rx[b]));
                __half2 h01 = *reinterpret_cast<__half2*>(&v.x);
                __half2 h23 = *reinterpret_cast<__half2*>(&v.y);
                f0[b] = __half22float2(h01);
                f1[b] = __half22float2(h23);
            }
            float r0 = Wx[0]*f0[0].x; r0 = fmaf(Wx[1], f0[1].x, r0);
            r0 = fmaf(Wx[2], f0[2].x, r0); r0 = fmaf(Wx[3], f0[3].x, r0);
            float r1 = Wx[0]*f0[0].y; r1 = fmaf(Wx[1], f0[1].y, r1);
            r1 = fmaf(Wx[2], f0[2].y, r1); r1 = fmaf(Wx[3], f0[3].y, r1);
            float r2 = Wx[0]*f1[0].x; r2 = fmaf(Wx[1], f1[1].x, r2);
            r2 = fmaf(Wx[2], f1[2].x, r2); r2 = fmaf(Wx[3], f1[3].x, r2);
            float r3 = Wx[0]*f1[0].y; r3 = fmaf(Wx[1], f1[1].y, r3);
            r3 = fmaf(Wx[2], f1[2].y, r3); r3 = fmaf(Wx[3], f1[3].y, r3);
            s0 = fmaf(Wy[a], r0, s0);
            s1 = fmaf(Wy[a], r1, s1);
            s2 = fmaf(Wy[a], r2, s2);
            s3 = fmaf(Wy[a], r3, s3);
        }
        __stcs(out + (g*4 + 0)*HW + oidx, s0);
        __stcs(out + (g*4 + 1)*HW + oidx, s1);
        __stcs(out + (g*4 + 2)*HW + oidx, s2);
        __stcs(out + (g*4 + 3)*HW + oidx, s3);
    }
}

extern "C" void kernel_launch(void* const* d_in, const int* in_sizes, int n_in,
                              void* d_out, int out_size) {
    const float* image = (const float*)d_in[0];
    const float* mask  = (const float*)d_in[1];
    const float* disp  = (const float*)d_in[2];
    float* out = (float*)d_out;

    table_kernel<<<4, 256>>>(disp);
    rowfilt_kernel<<<2048, 256>>>(image);
    colfilt_kernel<<<dim3(16, 32, 4), 256>>>();
    eval_kernel<<<dim3(4, 1024), 256>>>(mask, out);
}

// round 16
// speedup vs baseline: 1.5660x; 1.0267x over previous
#include <cuda_runtime.h>
#include <cuda_fp16.h>
#include <math.h>

#define Hh 1024
#define Ww 1024
#define Cc 16
#define HW (1024*1024)

#define ZD (-0.26794919243112270647)   // sqrt(3) - 2

static __device__ __half g_tmp[Cc*HW];     // row-filtered image fp16 (plane layout)
static __device__ __half g_coefh[Cc*HW];   // prefiltered coefs fp16, [group][y][x][4ch]
static __device__ float4 g_wy4[1024];      // strict cubic weights per coordinate
static __device__ int    g_myp[1024];      // packed mirrored indices (2 bits x 4)
static __device__ float  g_R[6*1024];      // folded x-dir displacement rows [ch*3+j][x]

// --- exact reference 3-point spline_filter1d (horizon = 3), eager-mode fp32 --
__device__ __forceinline__ void filt3(float v0, float v1, float v2, float* o) {
    const float Zf    = (float)ZD;
    const float Z2f   = (float)(ZD*ZD);
    const float GAIN  = 6.0f;                      // (1-z)(1-1/z) = 6 exactly
    const float LASTC = (float)(ZD/(ZD*ZD-1.0));
    float c0 = __fmul_rn(v0, GAIN);
    float c1 = __fmul_rn(v1, GAIN);
    float c2 = __fmul_rn(v2, GAIN);
    float cp0 = c0;
    cp0 = __fmaf_rn(Zf,  c1, cp0);
    cp0 = __fmaf_rn(Z2f, c2, cp0);
    float cp1 = __fadd_rn(c1, __fmul_rn(Zf, cp0));
    float cp2 = __fadd_rn(c2, __fmul_rn(Zf, cp1));
    float last = __fmul_rn(LASTC, __fadd_rn(cp2, __fmul_rn(Zf, cp1)));
    float o1 = __fmul_rn(Zf, __fsub_rn(last, cp1));
    float o0 = __fmul_rn(Zf, __fsub_rn(o1,  cp0));
    o[0] = o0; o[1] = o1; o[2] = last;
}

// --- strict (eager-jax) cubic weights ----------------------------------------
__device__ __forceinline__ void cubw_strict(float f, float* w) {
    float f2 = __fmul_rn(f, f);
    float f3 = __fmul_rn(f2, f);
    float t = __fsub_rn(1.0f, __fmul_rn(3.0f, f));
    t = __fadd_rn(t, __fmul_rn(3.0f, f2));
    t = __fsub_rn(t, f3);
    w[0] = __fdiv_rn(t, 6.0f);
    t = __fsub_rn(4.0f, __fmul_rn(6.0f, f2));
    t = __fadd_rn(t, __fmul_rn(3.0f, f3));
    w[1] = __fdiv_rn(t, 6.0f);
    t = __fadd_rn(1.0f, __fmul_rn(3.0f, f));
    t = __fadd_rn(t, __fmul_rn(3.0f, f2));
    t = __fsub_rn(t, __fmul_rn(3.0f, f3));
    w[2] = __fdiv_rn(t, 6.0f);
    w[3] = __fdiv_rn(f3, 6.0f);
}

__device__ __forceinline__ int mir3(int i) {        // mirror, n=3 (period 4)
    int m = i < 0 ? -i : i;
    m &= 3;
    return m > 2 ? 4 - m : m;
}
__device__ __forceinline__ int refl1024(int i) {    // mirror, n=1024 (small excursions)
    return i < 0 ? -i : (i > 1023 ? 2046 - i : i);
}

// --- fused setup + strict tables ----------------------------------------------
__global__ void table_kernel(const float* __restrict__ disp) {
    __shared__ float dcoef[18];
    if (threadIdx.x == 0) {
        float d[2][3][3];
        for (int ch = 0; ch < 2; ch++)
            for (int i = 0; i < 3; i++)
                for (int j = 0; j < 3; j++)
                    d[ch][i][j] = __fmul_rn(disp[ch*9 + i*3 + j], 10.0f);   // SIGMA
        for (int ch = 0; ch < 2; ch++)
            for (int j = 0; j < 3; j++) {
                float o[3];
                filt3(d[ch][0][j], d[ch][1][j], d[ch][2][j], o);
                d[ch][0][j] = o[0]; d[ch][1][j] = o[1]; d[ch][2][j] = o[2];
            }
        for (int ch = 0; ch < 2; ch++)
            for (int i = 0; i < 3; i++) {
                float o[3];
                filt3(d[ch][i][0], d[ch][i][1], d[ch][i][2], o);
                dcoef[ch*9 + i*3 + 0] = o[0];
                dcoef[ch*9 + i*3 + 1] = o[1];
                dcoef[ch*9 + i*3 + 2] = o[2];
            }
    }
    __syncthreads();

    int i = blockIdx.x * 256 + threadIdx.x;         // coordinate 0..1023
    const float SCL = (float)(2.0/1023.0);
    float u = __fmul_rn((float)i, SCL);
    float fl = floorf(u); int i0 = (int)fl;
    float f = __fsub_rn(u, fl);
    float w[4];
    cubw_strict(f, w);
    int m[4];
    #pragma unroll
    for (int b = 0; b < 4; b++) m[b] = mir3(i0 + b - 1);
    g_wy4[i] = make_float4(w[0], w[1], w[2], w[3]);
    g_myp[i] = m[0] | (m[1] << 2) | (m[2] << 4) | (m[3] << 6);
    #pragma unroll
    for (int ch = 0; ch < 2; ch++)
        #pragma unroll
        for (int j = 0; j < 3; j++) {
            float r = 0.0f;
            #pragma unroll
            for (int b = 0; b < 4; b++)
                r = __fadd_rn(r, __fmul_rn(w[b], dcoef[ch*9 + j*3 + m[b]]));
            g_R[(ch*3 + j)*1024 + i] = r;
        }
}

// --- strict dense field at (y, x) — verified bit-identical to reference ------
__device__ __forceinline__ void dense_field(int x, int y, float& sy, float& sx) {
    float4 wy = g_wy4[y];
    int mp = g_myp[y];
    const float* Rx = g_R + x;
    float d0 = 0.0f, d1 = 0.0f;
    int j;
    j = mp & 3;
    d0 = __fadd_rn(d0, __fmul_rn(wy.x, __ldg(Rx + j*1024)));
    d1 = __fadd_rn(d1, __fmul_rn(wy.x, __ldg(Rx + (3+j)*1024)));
    j = (mp >> 2) & 3;
    d0 = __fadd_rn(d0, __fmul_rn(wy.y, __ldg(Rx + j*1024)));
    d1 = __fadd_rn(d1, __fmul_rn(wy.y, __ldg(Rx + (3+j)*1024)));
    j = (mp >> 4) & 3;
    d0 = __fadd_rn(d0, __fmul_rn(wy.z, __ldg(Rx + j*1024)));
    d1 = __fadd_rn(d1, __fmul_rn(wy.z, __ldg(Rx + (3+j)*1024)));
    j = (mp >> 6) & 3;
    d0 = __fadd_rn(d0, __fmul_rn(wy.w, __ldg(Rx + j*1024)));
    d1 = __fadd_rn(d1, __fmul_rn(wy.w, __ldg(Rx + (3+j)*1024)));
    sy = __fadd_rn((float)y, d0);
    sx = __fadd_rn((float)x, d1);
}

// fp32 z^e via binary-power product (e in 0..127; z^128 flushed to 0)
__device__ __forceinline__ float zpowf(int e) {
    const float zb1  = (float)ZD;
    const float zb2  = zb1*zb1;
    const float zb4  = zb2*zb2;
    const float zb8  = zb4*zb4;
    const float zb16 = zb8*zb8;
    const float zb32 = zb16*zb16;
    const float zb64 = zb32*zb32;
    float r = 1.0f;
    if (e & 1)  r *= zb1;
    if (e & 2)  r *= zb2;
    if (e & 4)  r *= zb4;
    if (e & 8)  r *= zb8;
    if (e & 16) r *= zb16;
    if (e & 32) r *= zb32;
    if (e & 64) r *= zb64;
    if (e & 128) r = 0.0f;
    return r;
}

// --- row prefilter: block-serial scan, lane owns 4 consecutive elements ------
__global__ void __launch_bounds__(256) rowfilt_kernel(const float* __restrict__ img) {
    int warp = blockIdx.x * 8 + (threadIdx.x >> 5);   // row id: c*1024 + y
    int lane = threadIdx.x & 31;
    const float4* row4 = (const float4*)(img + warp * Ww);
    __half* orow = g_tmp + warp * Ww;

    const float z1  = (float)ZD;
    const float z2f = (float)(ZD*ZD);
    const float z3f = (float)(ZD*ZD*ZD);
    const float z4f = (float)(ZD*ZD*ZD*ZD);
    const float z8f  = z4f*z4f;
    const float z16f = z8f*z8f;
    const float z32f = z16f*z16f;
    const float z64f = z32f*z32f;
    const float SQ3 = (float)((1.0-ZD)/(1.0+ZD));   // sqrt(3)

    float zcw = zpowf(4*lane);          // z^(4*lane): causal block-carry weight
    float zaw = zpowf(124 - 4*lane);    // anticausal block-carry weight

    float xs[32], As[32];
    float carry = 0.0f;
    float A1022 = 0.0f;

    // ---- causal pass (forward) ----
    #pragma unroll
    for (int blk = 0; blk < 8; blk++) {
        float4 x = __ldg(row4 + blk*32 + lane);
        float a0 = x.x;
        float a1 = fmaf(z1, a0, x.y);
        float a2 = fmaf(z1, a1, x.z);
        float a3 = fmaf(z1, a2, x.w);
        float s = a3, v;
        v = __shfl_up_sync(0xffffffffu, s, 1);  if (lane >= 1)  s = fmaf(z4f,  v, s);
        v = __shfl_up_sync(0xffffffffu, s, 2);  if (lane >= 2)  s = fmaf(z8f,  v, s);
        v = __shfl_up_sync(0xffffffffu, s, 4);  if (lane >= 4)  s = fmaf(z16f, v, s);
        v = __shfl_up_sync(0xffffffffu, s, 8);  if (lane >= 8)  s = fmaf(z32f, v, s);
        v = __shfl_up_sync(0xffffffffu, s, 16); if (lane >= 16) s = fmaf(z64f, v, s);
        float seg = __shfl_up_sync(0xffffffffu, s, 1);
        seg = (lane == 0 ? 0.0f : seg) + zcw * carry;
        a0 = fmaf(z1,  seg, a0);
        a1 = fmaf(z2f, seg, a1);
        a2 = fmaf(z3f, seg, a2);
        a3 = fmaf(z4f, seg, a3);
        xs[blk*4+0] = x.x; xs[blk*4+1] = x.y; xs[blk*4+2] = x.z; xs[blk*4+3] = x.w;
        As[blk*4+0] = a0;  As[blk*4+1] = a1;  As[blk*4+2] = a2;  As[blk*4+3] = a3;
        carry = __shfl_sync(0xffffffffu, a3, 31);
        if (blk == 7) A1022 = __shfl_sync(0xffffffffu, a2, 31);  // state at e=1022
    }

    // ---- anticausal pass (backward) + combine + store ----
    float carryR = 0.0f;
    #pragma unroll
    for (int blk = 7; blk >= 0; blk--) {
        float x0 = xs[blk*4+0], x1 = xs[blk*4+1], x2 = xs[blk*4+2], x3 = xs[blk*4+3];
        float r3 = x3;
        float r2 = fmaf(z1, r3, x2);
        float r1 = fmaf(z1, r2, x1);
        float r0 = fmaf(z1, r1, x0);
        float s = r0, v;
        v = __shfl_down_sync(0xffffffffu, s, 1);  if (lane < 31) s = fmaf(z4f,  v, s);
        v = __shfl_down_sync(0xffffffffu, s, 2);  if (lane < 30) s = fmaf(z8f,  v, s);
        v = __shfl_down_sync(0xffffffffu, s, 4);  if (lane < 28) s = fmaf(z16f, v, s);
        v = __shfl_down_sync(0xffffffffu, s, 8);  if (lane < 24) s = fmaf(z32f, v, s);
        v = __shfl_down_sync(0xffffffffu, s, 16); if (lane < 16) s = fmaf(z64f, v, s);
        float segR = __shfl_down_sync(0xffffffffu, s, 1);
        segR = (lane == 31 ? 0.0f : segR) + zaw * carryR;
        r0 = fmaf(z4f, segR, r0);
        r1 = fmaf(z3f, segR, r1);
        r2 = fmaf(z2f, segR, r2);
        r3 = fmaf(z1,  segR, r3);
        carryR = __shfl_sync(0xffffffffu, r0, 0);

        float t0 = As[blk*4+0] + (r0 - x0);
        float t1 = As[blk*4+1] + (r1 - x1);
        float t2 = As[blk*4+2] + (r2 - x2);
        float t3 = As[blk*4+3] + (r3 - x3);
        if (blk == 7) {                       // right mirror: z^(1024-e) * A1022
            float w = zpowf(125 - 4*lane);
            t3 = fmaf(w, A1022, t3); w *= z1;
            t2 = fmaf(w, A1022, t2); w *= z1;
            t1 = fmaf(w, A1022, t1); w *= z1;
            t0 = fmaf(w, A1022, t0);
        }
        if (blk == 0) {                       // left mirror: z^e * B0
            float B0 = __shfl_sync(0xffffffffu, r0 - x0, 0);
            float w = zpowf(4*lane);
            t0 = fmaf(w, B0, t0); w *= z1;
            t1 = fmaf(w, B0, t1); w *= z1;
            t2 = fmaf(w, B0, t2); w *= z1;
            t3 = fmaf(w, B0, t3);
        }
        __half2 h01 = __halves2half2(__float2half_rn(SQ3*t0), __float2half_rn(SQ3*t1));
        __half2 h23 = __halves2half2(__float2half_rn(SQ3*t2), __float2half_rn(SQ3*t3));
        __half2* dst = (__half2*)(orow + blk*128 + lane*4);
        dst[0] = h01;
        dst[1] = h23;
    }
}

// --- column prefilter: halo 10 (z^10 ~ 2e-6 truncation), coalesced fp16 ------
__global__ void __launch_bounds__(256) colfilt_kernel() {
    int cl = threadIdx.x & 3;                  // channel within group
    int x  = blockIdx.x * 64 + (threadIdx.x >> 2);
    int g  = blockIdx.z;                       // channel group
    int c  = g*4 + cl;
    int ys = blockIdx.y * 32;
    const __half* base = g_tmp + c * HW + x;
    __half* ob = g_coefh + (size_t)g * 4 * HW + cl + 4 * (size_t)x;
    const float Zf  = (float)ZD;
    const float SQ3 = (float)((1.0-ZD)/(1.0+ZD));

    float A = 0.0f;
    #pragma unroll
    for (int j = 10; j >= 1; j--) {           // causal warm-up (mirror at top)
        int yy = ys - j; yy = yy < 0 ? -yy : yy;
        A = fmaf(Zf, A, __half2float(base[yy*Ww]));
    }
    float xs[32], As[32];
    #pragma unroll
    for (int j = 0; j < 32; j++) {
        float v = __half2float(base[(ys + j)*Ww]);
        A = fmaf(Zf, A, v);
        xs[j] = v; As[j] = A;
    }
    float R = 0.0f;
    #pragma unroll
    for (int j = 9; j >= 0; j--) {            // anticausal warm-up (mirror at bottom)
        int yy = ys + 32 + j; yy = yy > 1023 ? 2046 - yy : yy;
        R = fmaf(Zf, R, __half2float(base[yy*Ww]));
    }
    #pragma unroll
    for (int j = 31; j >= 0; j--) {
        ob[(size_t)(ys + j) * (4*Ww)] = __float2half_rn(SQ3 * fmaf(Zf, R, As[j]));
        R = fmaf(Zf, R, xs[j]);
    }
}

// fast weights for the image gather (loose tolerance path)
__device__ __forceinline__ void cubw_fast(float f, float* w) {
    float f2 = f*f;
    float f3 = f2*f;
    const float S = 1.0f/6.0f;
    w[0] = (1.0f - 3.0f*f + 3.0f*f2 - f3) * S;
    w[1] = (4.0f - 6.0f*f2 + 3.0f*f3) * S;
    w[2] = (1.0f + 3.0f*f + 3.0f*f2 - 3.0f*f3) * S;
    w[3] = f3 * S;
}

// --- monolithic eval (round-14 verified): strict field + fp16 gather ---------
// grid transposed: blockIdx.x = y (consecutive blocks share 3/4 coef tap-rows)
__global__ void __launch_bounds__(256, 4) eval_kernel(const float* __restrict__ mask,
                                                      float* __restrict__ out) {
    int x = blockIdx.y * 256 + threadIdx.x;
    int y = blockIdx.x;

    float sy, sx;
    dense_field(x, y, sy, sx);
    bool valid = (sy >= 0.0f) && (sy <= 1023.0f) && (sx >= 0.0f) && (sx <= 1023.0f);
    int oidx = y*Ww + x;

    if (!valid) {
        #pragma unroll
        for (int c = 0; c < 2*Cc; c++)
            out[c*HW + oidx] = 0.0f;
        return;
    }

    // ---- mask: nearest (half-even), verified --------------------------------
    {
        int ny = (int)rintf(sy); ny = ny < 0 ? 0 : (ny > 1023 ? 1023 : ny);
        int nx = (int)rintf(sx); nx = nx < 0 ? 0 : (nx > 1023 ? 1023 : nx);
        int midx = ny*Ww + nx;
        #pragma unroll
        for (int c = 0; c < Cc; c++)
            out[(Cc + c)*HW + oidx] = __ldg(mask + c*HW + midx);
    }

    // ---- image: fp16 channel-interleaved cubic gather, fp32 dot -------------
    float fs = floorf(sy); int iy = (int)fs; float fy = sy - fs;
    float gs = floorf(sx); int ix = (int)gs; float fx = sx - gs;
    float Wy[4], Wx[4];
    cubw_fast(fy, Wy); cubw_fast(fx, Wx);
    int ry[4], rx[4];
    #pragma unroll
    for (int a = 0; a < 4; a++) ry[a] = refl1024(iy + a - 1) * Ww;
    #pragma unroll
    for (int b = 0; b < 4; b++) rx[b] = refl1024(ix + b - 1);

    #pragma unroll
    for (int g = 0; g < 4; g++) {
        const __half* Ph = g_coefh + (size_t)g * 4 * HW;
        float s0 = 0.0f, s1 = 0.0f, s2 = 0.0f, s3 = 0.0f;
        #pragma unroll
        for (int a = 0; a < 4; a++) {
            const __half* pr = Ph + 4 * (size_t)ry[a];
            float2 f0[4], f1[4];
            #pragma unroll
            for (int b = 0; b < 4; b++) {
                uint2 v = __ldg((const uint2*)(pr + 4*rx[b]));
                __half2 h01 = *reinterpret_cast<__half2*>(&v.x);
                __half2 h23 = *reinterpret_cast<__half2*>(&v.y);
                f0[b] = __half22float2(h01);
                f1[b] = __half22float2(h23);
            }
            float r0 = Wx[0]*f0[0].x; r0 = fmaf(Wx[1], f0[1].x, r0);
            r0 = fmaf(Wx[2], f0[2].x, r0); r0 = fmaf(Wx[3], f0[3].x, r0);
            float r1 = Wx[0]*f0[0].y; r1 = fmaf(Wx[1], f0[1].y, r1);
            r1 = fmaf(Wx[2], f0[2].y, r1); r1 = fmaf(Wx[3], f0[3].y, r1);
            float r2 = Wx[0]*f1[0].x; r2 = fmaf(Wx[1], f1[1].x, r2);
            r2 = fmaf(Wx[2], f1[2].x, r2); r2 = fmaf(Wx[3], f1[3].x, r2);
            float r3 = Wx[0]*f1[0].y; r3 = fmaf(Wx[1], f1[1].y, r3);
            r3 = fmaf(Wx[2], f1[2].y, r3); r3 = fmaf(Wx[3], f1[3].y, r3);
            s0 = fmaf(Wy[a], r0, s0);
            s1 = fmaf(Wy[a], r1, s1);
            s2 = fmaf(Wy[a], r2, s2);
            s3 = fmaf(Wy[a], r3, s3);
        }
        out[(g*4 + 0)*HW + oidx] = s0;
        out[(g*4 + 1)*HW + oidx] = s1;
        out[(g*4 + 2)*HW + oidx] = s2;
        out[(g*4 + 3)*HW + oidx] = s3;
    }
}

extern "C" void kernel_launch(void* const* d_in, const int* in_sizes, int n_in,
                              void* d_out, int out_size) {
    const float* image = (const float*)d_in[0];
    const float* mask  = (const float*)d_in[1];
    const float* disp  = (const float*)d_in[2];
    float* out = (float*)d_out;

    table_kernel<<<4, 256>>>(disp);
    rowfilt_kernel<<<2048, 256>>>(image);
    colfilt_kernel<<<dim3(16, 32, 4), 256>>>();
    eval_kernel<<<dim3(1024, 4), 256>>>(mask, out);
}